// round 7
// baseline (speedup 1.0000x reference)
#include <cuda_runtime.h>
#include <cuda.h>
#include <cuda_fp16.h>
#include <cstdint>

// ============================================================================
// Problem constants
// ============================================================================
#define D_IN   4096
#define D_OUT  4096
#define MROWS  8192          // B*S = 4*2048
#define GROUPS 64            // D_IN / 64
#define RANK   16

// GEMM tiling (mma.sync path — compute_103 baseline, no tcgen05)
#define BM 128
#define BN 128
#define BK 64
#define STAGES 3
#define KITERS (D_IN / BK)                    // 64
#define NTILES_N (D_OUT / BN)                 // 32
#define NTILES  ((MROWS / BM) * NTILES_N)     // 2048
#define STG_A_BYTES (BM * BK * 2)             // 16384
#define STG_B_BYTES (BN * BK * 2)             // 16384
#define STG_STRIDE  (STG_A_BYTES + STG_B_BYTES) // 32768
#define STAGE_TX_BYTES STG_STRIDE

#define SMEM_FULL    0                         // 3 full mbarriers
#define SMEM_EMPTY   64                        // 3 empty mbarriers (count=4)
#define SMEM_TILES   1024
#define SMEM_TOTAL   (SMEM_TILES + STAGES * STG_STRIDE)  // 99328 -> 2 CTAs/SM

// ============================================================================
// Scratch (device globals — no allocation allowed)
// ============================================================================
__device__ __align__(1024) __half g_w16[(size_t)D_OUT * D_IN];   // W_eff fp16 [O, K]
__device__ __align__(1024) __half g_x16[(size_t)MROWS * D_IN];   // x fp16 [M, K]

// ============================================================================
// PTX helpers
// ============================================================================
__device__ __forceinline__ uint32_t smem_to_u32(const void* smem_ptr) {
    uint32_t addr;
    asm("{ .reg .u64 tmp; cvta.to.shared.u64 tmp, %1; cvt.u32.u64 %0, tmp; }"
        : "=r"(addr) : "l"(smem_ptr));
    return addr;
}

#define MBARRIER_INIT(mbar_smem_addr, count) \
    asm volatile("mbarrier.init.shared.b64 [%0], %1;" \
        :: "r"((uint32_t)(mbar_smem_addr)), "r"((uint32_t)(count)) : "memory")

#define MBARRIER_ARRIVE(mbar_smem_addr) \
    asm volatile("mbarrier.arrive.shared.b64 _, [%0];" \
        :: "r"((uint32_t)(mbar_smem_addr)) : "memory")

#define MBARRIER_EXPECT_TX(mbar_smem_addr, tx_bytes) \
    asm volatile("mbarrier.arrive.expect_tx.shared.b64 _, [%0], %1;" \
        :: "r"((uint32_t)(mbar_smem_addr)), "r"((uint32_t)(tx_bytes)) : "memory")

#define MBARRIER_WAIT_PARITY(mbar_smem_addr, phase_parity) do { \
    uint32_t _mbar = (uint32_t)(mbar_smem_addr); \
    uint32_t _parity = (uint32_t)(phase_parity); \
    uint32_t _done; \
    asm volatile( \
        "{\n\t" \
        ".reg .pred p;\n\t" \
        "mbarrier.try_wait.parity.acquire.cta.shared::cta.b64 p, [%1], %2;\n\t" \
        "selp.b32 %0, 1, 0, p;\n\t" \
        "}" \
        : "=r"(_done) : "r"(_mbar), "r"(_parity) : "memory"); \
    if (!_done) { \
        asm volatile( \
            "{\n\t" \
            ".reg .pred P1;\n\t" \
            "WAIT_LOOP_%=:\n\t" \
            "mbarrier.try_wait.parity.acquire.cta.shared::cta.b64 P1, [%0], %1, 0x989680;\n\t" \
            "@P1 bra.uni WAIT_DONE_%=;\n\t" \
            "bra.uni WAIT_LOOP_%=;\n\t" \
            "WAIT_DONE_%=:\n\t" \
            "}" \
            :: "r"(_mbar), "r"(_parity) : "memory"); \
    } \
} while(0)

#define TMA_LOAD_3D(smem_addr, tensor_map, coord_x, coord_y, coord_z, mbar_smem_addr) \
    asm volatile( \
        "cp.async.bulk.tensor.3d.shared::cta.global.tile.mbarrier::complete_tx::bytes " \
        "[%0], [%1, {%2, %3, %4}], [%5];" \
        :: "r"((uint32_t)(smem_addr)), "l"(tensor_map), "r"((int32_t)(coord_x)), \
           "r"((int32_t)(coord_y)), "r"((int32_t)(coord_z)), \
           "r"((uint32_t)(mbar_smem_addr)) \
        : "memory")

#define LDMATRIX_X4(r0, r1, r2, r3, addr) \
    asm volatile("ldmatrix.sync.aligned.m8n8.x4.shared.b16 {%0,%1,%2,%3}, [%4];" \
        : "=r"(r0), "=r"(r1), "=r"(r2), "=r"(r3) : "r"(addr))

#define MMA_16816(d, a, b0, b1) \
    asm volatile("mma.sync.aligned.m16n8k16.row.col.f32.f16.f16.f32 " \
        "{%0,%1,%2,%3}, {%4,%5,%6,%7}, {%8,%9}, {%0,%1,%2,%3};" \
        : "+f"((d)[0]), "+f"((d)[1]), "+f"((d)[2]), "+f"((d)[3]) \
        : "r"((a)[0]), "r"((a)[1]), "r"((a)[2]), "r"((a)[3]), "r"(b0), "r"(b1))

// ============================================================================
// Prep kernel 1: cast x (fp32 -> fp16), vectorized
// ============================================================================
__global__ void cast_x_kernel(const float4* __restrict__ x, uint2* __restrict__ y,
                              int n4) {
    int i = blockIdx.x * 256 + threadIdx.x;
    if (i < n4) {
        float4 v = x[i];
        __half2 a = __floats2half2_rn(v.x, v.y);
        __half2 b = __floats2half2_rn(v.z, v.w);
        uint2 o;
        o.x = *reinterpret_cast<unsigned*>(&a);
        o.y = *reinterpret_cast<unsigned*>(&b);
        y[i] = o;
    }
}

// ============================================================================
// Prep kernel 2: W_eff[o,i] = (q[o,i]-zeros[o,g])*scales[o,g] + (1/16)*(B@A)[o,i]
// ============================================================================
#define WB_OT 32
#define WB_IT 128
__global__ void build_w_kernel(const int* __restrict__ qw,
                               const float* __restrict__ sc,
                               const float* __restrict__ zr,
                               const float* __restrict__ lA,
                               const float* __restrict__ lB,
                               __half* __restrict__ W) {
    __shared__ float As[RANK][WB_IT];
    __shared__ float Bs[WB_OT][RANK];
    __shared__ float Ss[WB_OT][2];
    __shared__ float Zs[WB_OT][2];

    int i0 = blockIdx.x * WB_IT;
    int o0 = blockIdx.y * WB_OT;
    int t = threadIdx.x;

    for (int e = t; e < RANK * WB_IT; e += 256)
        As[e / WB_IT][e % WB_IT] = lA[(e / WB_IT) * D_IN + i0 + (e % WB_IT)];
    for (int e = t; e < WB_OT * RANK; e += 256)
        Bs[e / RANK][e % RANK] = lB[(size_t)(o0 + e / RANK) * RANK + (e % RANK)];
    int g0 = i0 / 64;
    if (t < WB_OT * 2) {
        int ol = t >> 1, gg = t & 1;
        Ss[ol][gg] = sc[(size_t)(o0 + ol) * GROUPS + g0 + gg];
        Zs[ol][gg] = zr[(size_t)(o0 + ol) * GROUPS + g0 + gg];
    }
    __syncthreads();

    #pragma unroll 4
    for (int k = 0; k < (WB_OT * WB_IT) / 256; k++) {
        int e = k * 256 + t;
        int ol = e >> 7;          // /128
        int il = e & 127;
        float qv = (float)qw[(size_t)(o0 + ol) * D_IN + i0 + il];
        float lora = 0.f;
        #pragma unroll
        for (int r = 0; r < RANK; r++) lora += Bs[ol][r] * As[r][il];
        int gg = il >> 6;
        float w = (qv - Zs[ol][gg]) * Ss[ol][gg] + 0.0625f * lora;
        W[(size_t)(o0 + ol) * D_IN + i0 + il] = __float2half_rn(w);
    }
}

// ============================================================================
// Persistent GEMM: out[m, n] = sum_k x16[m,k] * w16[n,k] + bias[n]
// grid = 2 * numSMs CTAs; each CTA loops over output tiles. The 3-stage TMA
// ring + producer warp run CONTINUOUSLY across tiles: epilogue and pipeline
// refill fully overlap with the next tile's loads.
// CTA 128x128, BK=64, mma.sync.m16n8k16 (fp32 accum).
// 4 compute warps (64x64 tiles) + 1 producer warp.
// ============================================================================
__global__ void __launch_bounds__(160, 2)
qlora_gemm_kernel(const __grid_constant__ CUtensorMap tmx,
                  const __grid_constant__ CUtensorMap tmw,
                  const float* __restrict__ bias,
                  float* __restrict__ out) {
    extern __shared__ __align__(1024) char smem[];
    uint32_t sb = smem_to_u32(smem);
    int tid = threadIdx.x;
    int wid = tid >> 5, lid = tid & 31;

    if (tid == 0) {
        #pragma unroll
        for (int s = 0; s < STAGES; s++) {
            MBARRIER_INIT(sb + SMEM_FULL + 8 * s, 1);
            MBARRIER_INIT(sb + SMEM_EMPTY + 8 * s, 4);
        }
    }
    __syncthreads();

    // ======================= producer warp (wid == 4) ======================
    if (wid == 4) {
        if (lid == 0) {
            int s = 0;
            uint32_t eph = 0;                 // per-stage phase bitmask
            long gi = 0;                      // global iteration counter
            for (int tile = blockIdx.x; tile < NTILES; tile += gridDim.x) {
                int n0 = (tile & (NTILES_N - 1)) * BN;
                int m0 = (tile / NTILES_N) * BM;
                for (int i = 0; i < KITERS; i++, gi++) {
                    if (gi >= STAGES) {
                        MBARRIER_WAIT_PARITY(sb + SMEM_EMPTY + 8 * s, (eph >> s) & 1);
                        eph ^= (1u << s);
                    }
                    uint32_t fb = sb + SMEM_FULL + 8 * s;
                    MBARRIER_EXPECT_TX(fb, STAGE_TX_BYTES);
                    uint32_t stile = sb + SMEM_TILES + s * STG_STRIDE;
                    TMA_LOAD_3D(stile,               &tmx, i * BK, m0, 0, fb);
                    TMA_LOAD_3D(stile + STG_A_BYTES, &tmw, i * BK, n0, 0, fb);
                    if (++s == STAGES) s = 0;
                }
            }
        }
        return;
    }

    // ======================= compute warps (wid 0..3) ======================
    int wm = wid & 1;        // m-offset wm*64
    int wn = wid >> 1;       // n-offset wn*64

    // ---- per-lane ldmatrix address precompute (SW128 swizzle) ----
    // swizzled(off) = off ^ ((off>>3)&0x70); off = row*128 + colbyte
    // → swizzled = row*128 + (colbyte ^ ((row&7)<<4))
    int j = lid & 7, blk = lid >> 3;

    int colA = (blk >> 1) << 4;                       // 0 or 16 bytes (k8*2B)
    uint32_t baseA[4], maskA[4];
    #pragma unroll
    for (int t = 0; t < 4; t++) {
        int rowA = wm * 64 + t * 16 + ((blk & 1) << 3) + j;
        baseA[t] = rowA * 128;
        maskA[t] = (rowA & 7) << 4;
    }

    int colB = (blk & 1) << 4;                        // 0 or 16 bytes
    uint32_t baseB[4], maskB[4];
    #pragma unroll
    for (int t = 0; t < 4; t++) {
        int rowB = wn * 64 + t * 16 + ((blk >> 1) << 3) + j;
        baseB[t] = rowB * 128;
        maskB[t] = (rowB & 7) << 4;
    }

    int qrow = lid >> 2;          // 0..7
    int qcol = (lid & 3) << 1;    // 0,2,4,6

    int s = 0;
    uint32_t fph = 0;             // per-stage phase bitmask (persists across tiles)

    for (int tile = blockIdx.x; tile < NTILES; tile += gridDim.x) {
        int n0 = (tile & (NTILES_N - 1)) * BN;
        int m0 = (tile / NTILES_N) * BM;

        float acc[4][8][4];
        #pragma unroll
        for (int a = 0; a < 4; a++)
            #pragma unroll
            for (int b = 0; b < 8; b++)
                #pragma unroll
                for (int c = 0; c < 4; c++) acc[a][b][c] = 0.f;

        // ---- k loop ----
        for (int i = 0; i < KITERS; i++) {
            MBARRIER_WAIT_PARITY(sb + SMEM_FULL + 8 * s, (fph >> s) & 1);
            fph ^= (1u << s);
            uint32_t sA = sb + SMEM_TILES + s * STG_STRIDE;
            uint32_t sB = sA + STG_A_BYTES;

            #pragma unroll
            for (int ks = 0; ks < BK / 16; ks++) {
                uint32_t kb = ks << 5;                // k-step byte offset
                uint32_t afr[4][4], bfr[4][4];
                #pragma unroll
                for (int t = 0; t < 4; t++)
                    LDMATRIX_X4(afr[t][0], afr[t][1], afr[t][2], afr[t][3],
                                sA + baseA[t] + ((kb + colA) ^ maskA[t]));
                #pragma unroll
                for (int t = 0; t < 4; t++)
                    LDMATRIX_X4(bfr[t][0], bfr[t][1], bfr[t][2], bfr[t][3],
                                sB + baseB[t] + ((kb + colB) ^ maskB[t]));
                #pragma unroll
                for (int mt = 0; mt < 4; mt++) {
                    #pragma unroll
                    for (int t = 0; t < 4; t++) {
                        MMA_16816(acc[mt][2 * t + 0], afr[mt], bfr[t][0], bfr[t][1]);
                        MMA_16816(acc[mt][2 * t + 1], afr[mt], bfr[t][2], bfr[t][3]);
                    }
                }
            }

            if (lid == 0) MBARRIER_ARRIVE(sb + SMEM_EMPTY + 8 * s);
            if (++s == STAGES) s = 0;
        }

        // ---- epilogue (producer keeps prefetching next tile meanwhile) ----
        #pragma unroll
        for (int mt = 0; mt < 4; mt++) {
            int r0 = m0 + wm * 64 + mt * 16 + qrow;
            #pragma unroll
            for (int nt = 0; nt < 8; nt++) {
                int c = n0 + wn * 64 + nt * 8 + qcol;
                float2 bv = *reinterpret_cast<const float2*>(bias + c);
                float2 v0, v1;
                v0.x = acc[mt][nt][0] + bv.x;
                v0.y = acc[mt][nt][1] + bv.y;
                v1.x = acc[mt][nt][2] + bv.x;
                v1.y = acc[mt][nt][3] + bv.y;
                *reinterpret_cast<float2*>(out + (size_t)r0 * D_OUT + c) = v0;
                *reinterpret_cast<float2*>(out + (size_t)(r0 + 8) * D_OUT + c) = v1;
            }
        }
    }
}

// ============================================================================
// Host launch
// ============================================================================
typedef CUresult (*tmap_encode_fn)(
    CUtensorMap*, CUtensorMapDataType, cuuint32_t, void*,
    const cuuint64_t*, const cuuint64_t*, const cuuint32_t*, const cuuint32_t*,
    CUtensorMapInterleave, CUtensorMapSwizzle, CUtensorMapL2promotion,
    CUtensorMapFloatOOBfill);

extern "C" void kernel_launch(void* const* d_in, const int* in_sizes, int n_in,
                              void* d_out, int out_size) {
    const float* x    = (const float*)d_in[0];
    const int*   qw   = (const int*)d_in[1];
    const float* sc   = (const float*)d_in[2];
    const float* zr   = (const float*)d_in[3];
    const float* lA   = (const float*)d_in[4];
    const float* lB   = (const float*)d_in[5];
    const float* bias = (const float*)d_in[6];
    float* out = (float*)d_out;

    void* x16p = nullptr;
    void* w16p = nullptr;
    cudaGetSymbolAddress(&x16p, g_x16);
    cudaGetSymbolAddress(&w16p, g_w16);

    tmap_encode_fn enc = nullptr;
    cudaDriverEntryPointQueryResult qres;
    cudaGetDriverEntryPointByVersion("cuTensorMapEncodeTiled", (void**)&enc,
                                     12000, cudaEnableDefault, &qres);
    if (!enc) return;

    CUtensorMap tmx, tmw;
    {
        cuuint64_t dims[3]    = {D_IN, MROWS, 1};
        cuuint64_t strides[2] = {(cuuint64_t)D_IN * 2, (cuuint64_t)D_IN * MROWS * 2};
        cuuint32_t box[3]     = {BK, BM, 1};
        cuuint32_t es[3]      = {1, 1, 1};
        enc(&tmx, CU_TENSOR_MAP_DATA_TYPE_FLOAT16, 3, x16p, dims, strides, box, es,
            CU_TENSOR_MAP_INTERLEAVE_NONE, CU_TENSOR_MAP_SWIZZLE_128B,
            CU_TENSOR_MAP_L2_PROMOTION_L2_128B, CU_TENSOR_MAP_FLOAT_OOB_FILL_NONE);
    }
    {
        cuuint64_t dims[3]    = {D_IN, D_OUT, 1};
        cuuint64_t strides[2] = {(cuuint64_t)D_IN * 2, (cuuint64_t)D_IN * D_OUT * 2};
        cuuint32_t box[3]     = {BK, BN, 1};
        cuuint32_t es[3]      = {1, 1, 1};
        enc(&tmw, CU_TENSOR_MAP_DATA_TYPE_FLOAT16, 3, w16p, dims, strides, box, es,
            CU_TENSOR_MAP_INTERLEAVE_NONE, CU_TENSOR_MAP_SWIZZLE_128B,
            CU_TENSOR_MAP_L2_PROMOTION_L2_128B, CU_TENSOR_MAP_FLOAT_OOB_FILL_NONE);
    }

    // 1) cast x -> fp16
    int n4 = (MROWS * D_IN) / 4;
    cast_x_kernel<<<(n4 + 255) / 256, 256>>>((const float4*)x, (uint2*)x16p, n4);

    // 2) dequant + LoRA fold -> W_eff fp16
    build_w_kernel<<<dim3(D_IN / WB_IT, D_OUT / WB_OT), 256>>>(
        qw, sc, zr, lA, lB, (__half*)w16p);

    // 3) persistent GEMM + bias (grid = 2 CTAs per SM)
    int nsm = 148;
    cudaDeviceGetAttribute(&nsm, cudaDevAttrMultiProcessorCount, 0);
    int grid = 2 * nsm;
    if (grid > NTILES) grid = NTILES;
    cudaFuncSetAttribute(qlora_gemm_kernel,
                         cudaFuncAttributeMaxDynamicSharedMemorySize, SMEM_TOTAL);
    qlora_gemm_kernel<<<grid, 160, SMEM_TOTAL>>>(tmx, tmw, bias, out);
}

// round 9
// speedup vs baseline: 1.1521x; 1.1521x over previous
#include <cuda_runtime.h>
#include <cuda.h>
#include <cuda_fp16.h>
#include <cstdint>

// ============================================================================
// Problem constants
// ============================================================================
#define D_IN   4096
#define D_OUT  4096
#define MROWS  8192          // B*S = 4*2048
#define GROUPS 64            // D_IN / 64
#define RANK   16

// GEMM tiling (mma.sync path — compute_103 baseline, no tcgen05)
#define BM 128
#define BN 128
#define BK 64
#define STAGES 3
#define KITERS (D_IN / BK)                    // 64
#define STG_A_BYTES (BM * BK * 2)             // 16384
#define STG_B_BYTES (BN * BK * 2)             // 16384
#define STG_STRIDE  (STG_A_BYTES + STG_B_BYTES) // 32768
#define STAGE_TX_BYTES STG_STRIDE

#define SMEM_FULL    0                         // 3 full mbarriers
#define SMEM_TILES   1024
#define SMEM_TOTAL   (SMEM_TILES + STAGES * STG_STRIDE)  // 99328 -> 2 CTAs/SM

// ============================================================================
// Scratch (device globals — no allocation allowed)
// ============================================================================
__device__ __align__(1024) __half g_w16[(size_t)D_OUT * D_IN];   // W_eff fp16 [O, K]
__device__ __align__(1024) __half g_x16[(size_t)MROWS * D_IN];   // x fp16 [M, K]

// ============================================================================
// PTX helpers
// ============================================================================
__device__ __forceinline__ uint32_t smem_to_u32(const void* smem_ptr) {
    uint32_t addr;
    asm("{ .reg .u64 tmp; cvta.to.shared.u64 tmp, %1; cvt.u32.u64 %0, tmp; }"
        : "=r"(addr) : "l"(smem_ptr));
    return addr;
}

#define MBARRIER_INIT(mbar_smem_addr, count) \
    asm volatile("mbarrier.init.shared.b64 [%0], %1;" \
        :: "r"((uint32_t)(mbar_smem_addr)), "r"((uint32_t)(count)) : "memory")

#define MBARRIER_EXPECT_TX(mbar_smem_addr, tx_bytes) \
    asm volatile("mbarrier.arrive.expect_tx.shared.b64 _, [%0], %1;" \
        :: "r"((uint32_t)(mbar_smem_addr)), "r"((uint32_t)(tx_bytes)) : "memory")

#define MBARRIER_WAIT_PARITY(mbar_smem_addr, phase_parity) do { \
    uint32_t _mbar = (uint32_t)(mbar_smem_addr); \
    uint32_t _parity = (uint32_t)(phase_parity); \
    uint32_t _done; \
    asm volatile( \
        "{\n\t" \
        ".reg .pred p;\n\t" \
        "mbarrier.try_wait.parity.acquire.cta.shared::cta.b64 p, [%1], %2;\n\t" \
        "selp.b32 %0, 1, 0, p;\n\t" \
        "}" \
        : "=r"(_done) : "r"(_mbar), "r"(_parity) : "memory"); \
    if (!_done) { \
        asm volatile( \
            "{\n\t" \
            ".reg .pred P1;\n\t" \
            "WAIT_LOOP_%=:\n\t" \
            "mbarrier.try_wait.parity.acquire.cta.shared::cta.b64 P1, [%0], %1, 0x989680;\n\t" \
            "@P1 bra.uni WAIT_DONE_%=;\n\t" \
            "bra.uni WAIT_LOOP_%=;\n\t" \
            "WAIT_DONE_%=:\n\t" \
            "}" \
            :: "r"(_mbar), "r"(_parity) : "memory"); \
    } \
} while(0)

#define TMA_LOAD_3D(smem_addr, tensor_map, coord_x, coord_y, coord_z, mbar_smem_addr) \
    asm volatile( \
        "cp.async.bulk.tensor.3d.shared::cta.global.tile.mbarrier::complete_tx::bytes " \
        "[%0], [%1, {%2, %3, %4}], [%5];" \
        :: "r"((uint32_t)(smem_addr)), "l"(tensor_map), "r"((int32_t)(coord_x)), \
           "r"((int32_t)(coord_y)), "r"((int32_t)(coord_z)), \
           "r"((uint32_t)(mbar_smem_addr)) \
        : "memory")

#define LDMATRIX_X4(r0, r1, r2, r3, addr) \
    asm volatile("ldmatrix.sync.aligned.m8n8.x4.shared.b16 {%0,%1,%2,%3}, [%4];" \
        : "=r"(r0), "=r"(r1), "=r"(r2), "=r"(r3) : "r"(addr))

#define MMA_16816(d, a, b0, b1) \
    asm volatile("mma.sync.aligned.m16n8k16.row.col.f32.f16.f16.f32 " \
        "{%0,%1,%2,%3}, {%4,%5,%6,%7}, {%8,%9}, {%0,%1,%2,%3};" \
        : "+f"((d)[0]), "+f"((d)[1]), "+f"((d)[2]), "+f"((d)[3]) \
        : "r"((a)[0]), "r"((a)[1]), "r"((a)[2]), "r"((a)[3]), "r"(b0), "r"(b1))

// Streaming (evict-first) float2 store: keeps W/x tiles resident in L2.
#define STG_CS_V2F32(ptr, vx, vy) \
    asm volatile("st.global.cs.v2.f32 [%0], {%1, %2};" \
        :: "l"(ptr), "f"(vx), "f"(vy) : "memory")

// ============================================================================
// Prep kernel 1: cast x (fp32 -> fp16). Each thread: 2 float4 in, 1 uint4 out.
// ============================================================================
__global__ void __launch_bounds__(256)
cast_x_kernel(const float4* __restrict__ x, uint4* __restrict__ y, int n8) {
    int i = blockIdx.x * 256 + threadIdx.x;
    if (i < n8) {
        float4 v0 = x[2 * i + 0];
        float4 v1 = x[2 * i + 1];
        __half2 a = __floats2half2_rn(v0.x, v0.y);
        __half2 b = __floats2half2_rn(v0.z, v0.w);
        __half2 c = __floats2half2_rn(v1.x, v1.y);
        __half2 d = __floats2half2_rn(v1.z, v1.w);
        uint4 o;
        o.x = *reinterpret_cast<unsigned*>(&a);
        o.y = *reinterpret_cast<unsigned*>(&b);
        o.z = *reinterpret_cast<unsigned*>(&c);
        o.w = *reinterpret_cast<unsigned*>(&d);
        y[i] = o;
    }
}

// ============================================================================
// Prep kernel 2: W_eff[o,i] = (q[o,i]-zeros[o,g])*scales[o,g] + (1/16)*(B@A)[o,i]
// int4 qweight loads, uint2 (2x half2) stores. Tile 32(o) x 128(i), 256 thr.
// ============================================================================
#define WB_OT 32
#define WB_IT 128
__global__ void __launch_bounds__(256)
build_w_kernel(const int4* __restrict__ qw4,
               const float* __restrict__ sc,
               const float* __restrict__ zr,
               const float* __restrict__ lA,
               const float* __restrict__ lB,
               uint2* __restrict__ W2) {
    __shared__ float As[RANK][WB_IT];
    __shared__ float Bs[WB_OT][RANK];
    __shared__ float Ss[WB_OT][2];
    __shared__ float Zs[WB_OT][2];

    int i0 = blockIdx.x * WB_IT;
    int o0 = blockIdx.y * WB_OT;
    int t = threadIdx.x;

    for (int e = t; e < RANK * WB_IT; e += 256)
        As[e / WB_IT][e % WB_IT] = lA[(e / WB_IT) * D_IN + i0 + (e % WB_IT)];
    for (int e = t; e < WB_OT * RANK; e += 256)
        Bs[e / RANK][e % RANK] = lB[(size_t)(o0 + e / RANK) * RANK + (e % RANK)];
    int g0 = i0 / 64;
    if (t < WB_OT * 2) {
        int ol = t >> 1, gg = t & 1;
        Ss[ol][gg] = sc[(size_t)(o0 + ol) * GROUPS + g0 + gg];
        Zs[ol][gg] = zr[(size_t)(o0 + ol) * GROUPS + g0 + gg];
    }
    __syncthreads();

    // 4096 elements / (256 thr * 4 elem) = 4 passes
    #pragma unroll
    for (int k = 0; k < (WB_OT * WB_IT) / (256 * 4); k++) {
        int e = (k * 256 + t) * 4;          // element index in tile
        int ol = e >> 7;                    // /128
        int il = e & 127;                   // multiple of 4
        int gg = il >> 6;
        float s = Ss[ol][gg], z = Zs[ol][gg];

        int4 q4 = qw4[((size_t)(o0 + ol) * D_IN + i0 + il) >> 2];
        float w[4];
        w[0] = ((float)q4.x - z) * s;
        w[1] = ((float)q4.y - z) * s;
        w[2] = ((float)q4.z - z) * s;
        w[3] = ((float)q4.w - z) * s;
        #pragma unroll
        for (int r = 0; r < RANK; r++) {
            float b = Bs[ol][r] * 0.0625f;
            w[0] += b * As[r][il + 0];
            w[1] += b * As[r][il + 1];
            w[2] += b * As[r][il + 2];
            w[3] += b * As[r][il + 3];
        }
        __half2 p0 = __floats2half2_rn(w[0], w[1]);
        __half2 p1 = __floats2half2_rn(w[2], w[3]);
        uint2 o;
        o.x = *reinterpret_cast<unsigned*>(&p0);
        o.y = *reinterpret_cast<unsigned*>(&p1);
        W2[((size_t)(o0 + ol) * D_IN + i0 + il) >> 2] = o;
    }
}

// ============================================================================
// GEMM: out[m, n] = sum_k x16[m,k] * w16[n,k] + bias[n]
// CTA 128x128, BK=64, 3-stage TMA pipeline, mma.sync.m16n8k16 (fp32 accum).
// 4 warps (one per SMSP): warp grid 2(m) x 2(n); warp tile 64 x 64.
// 2 CTAs/SM. Epilogue uses streaming stores (evict-first) to protect L2.
// ============================================================================
__global__ void __launch_bounds__(128, 2)
qlora_gemm_kernel(const __grid_constant__ CUtensorMap tmx,
                  const __grid_constant__ CUtensorMap tmw,
                  const float* __restrict__ bias,
                  float* __restrict__ out) {
    extern __shared__ __align__(1024) char smem[];
    uint32_t sb = smem_to_u32(smem);
    int tid = threadIdx.x;
    int wid = tid >> 5, lid = tid & 31;
    int wm = wid & 1;        // m-offset wm*64
    int wn = wid >> 1;       // n-offset wn*64
    int n0 = blockIdx.x * BN;
    int m0 = blockIdx.y * BM;

    if (tid == 0) {
        #pragma unroll
        for (int s = 0; s < STAGES; s++)
            MBARRIER_INIT(sb + SMEM_FULL + 8 * s, 1);
    }
    __syncthreads();

    // Prologue: prefetch first STAGES tiles (elected thread)
    if (tid == 0) {
        #pragma unroll
        for (int s = 0; s < STAGES; s++) {
            uint32_t fb = sb + SMEM_FULL + 8 * s;
            MBARRIER_EXPECT_TX(fb, STAGE_TX_BYTES);
            uint32_t tile = sb + SMEM_TILES + s * STG_STRIDE;
            TMA_LOAD_3D(tile,               &tmx, s * BK, m0, 0, fb);
            TMA_LOAD_3D(tile + STG_A_BYTES, &tmw, s * BK, n0, 0, fb);
        }
    }

    // ---- per-lane ldmatrix address precompute (SW128 swizzle) ----
    // swizzled(off) = off ^ ((off>>3)&0x70); off = row*128 + colbyte
    // → swizzled = row*128 + (colbyte ^ ((row&7)<<4))
    int j = lid & 7, blk = lid >> 3;

    int colA = (blk >> 1) << 4;                       // 0 or 16 bytes (k8*2B)
    uint32_t baseA[4], maskA[4];
    #pragma unroll
    for (int t = 0; t < 4; t++) {
        int rowA = wm * 64 + t * 16 + ((blk & 1) << 3) + j;
        baseA[t] = rowA * 128;
        maskA[t] = (rowA & 7) << 4;
    }

    int colB = (blk & 1) << 4;                        // 0 or 16 bytes
    uint32_t baseB[4], maskB[4];
    #pragma unroll
    for (int t = 0; t < 4; t++) {
        int rowB = wn * 64 + t * 16 + ((blk >> 1) << 3) + j;
        baseB[t] = rowB * 128;
        maskB[t] = (rowB & 7) << 4;
    }

    float acc[4][8][4];
    #pragma unroll
    for (int a = 0; a < 4; a++)
        #pragma unroll
        for (int b = 0; b < 8; b++)
            #pragma unroll
            for (int c = 0; c < 4; c++) acc[a][b][c] = 0.f;

    // ---- main loop ----
    int s = 0, phase = 0;
    for (int i = 0; i < KITERS; i++) {
        MBARRIER_WAIT_PARITY(sb + SMEM_FULL + 8 * s, phase);
        uint32_t sA = sb + SMEM_TILES + s * STG_STRIDE;
        uint32_t sB = sA + STG_A_BYTES;

        #pragma unroll
        for (int ks = 0; ks < BK / 16; ks++) {
            uint32_t kb = ks << 5;                    // k-step byte offset (k16*2B)
            uint32_t afr[4][4], bfr[4][4];
            #pragma unroll
            for (int t = 0; t < 4; t++)
                LDMATRIX_X4(afr[t][0], afr[t][1], afr[t][2], afr[t][3],
                            sA + baseA[t] + ((kb + colA) ^ maskA[t]));
            #pragma unroll
            for (int t = 0; t < 4; t++)
                LDMATRIX_X4(bfr[t][0], bfr[t][1], bfr[t][2], bfr[t][3],
                            sB + baseB[t] + ((kb + colB) ^ maskB[t]));
            #pragma unroll
            for (int mt = 0; mt < 4; mt++) {
                #pragma unroll
                for (int t = 0; t < 4; t++) {
                    MMA_16816(acc[mt][2 * t + 0], afr[mt], bfr[t][0], bfr[t][1]);
                    MMA_16816(acc[mt][2 * t + 1], afr[mt], bfr[t][2], bfr[t][3]);
                }
            }
        }

        __syncthreads();   // all warps done reading stage s
        if (tid == 0 && i + STAGES < KITERS) {
            uint32_t fb = sb + SMEM_FULL + 8 * s;
            MBARRIER_EXPECT_TX(fb, STAGE_TX_BYTES);
            uint32_t tile = sb + SMEM_TILES + s * STG_STRIDE;
            TMA_LOAD_3D(tile,               &tmx, (i + STAGES) * BK, m0, 0, fb);
            TMA_LOAD_3D(tile + STG_A_BYTES, &tmw, (i + STAGES) * BK, n0, 0, fb);
        }
        if (++s == STAGES) { s = 0; phase ^= 1; }
    }

    // ---- epilogue: register -> gmem with bias, streaming stores ----
    int qrow = lid >> 2;          // 0..7
    int qcol = (lid & 3) << 1;    // 0,2,4,6
    #pragma unroll
    for (int mt = 0; mt < 4; mt++) {
        int r0 = m0 + wm * 64 + mt * 16 + qrow;
        #pragma unroll
        for (int nt = 0; nt < 8; nt++) {
            int c = n0 + wn * 64 + nt * 8 + qcol;
            float2 bv = *reinterpret_cast<const float2*>(bias + c);
            float* p0 = out + (size_t)r0 * D_OUT + c;
            float* p1 = out + (size_t)(r0 + 8) * D_OUT + c;
            STG_CS_V2F32(p0, acc[mt][nt][0] + bv.x, acc[mt][nt][1] + bv.y);
            STG_CS_V2F32(p1, acc[mt][nt][2] + bv.x, acc[mt][nt][3] + bv.y);
        }
    }
}

// ============================================================================
// Host launch
// ============================================================================
typedef CUresult (*tmap_encode_fn)(
    CUtensorMap*, CUtensorMapDataType, cuuint32_t, void*,
    const cuuint64_t*, const cuuint64_t*, const cuuint32_t*, const cuuint32_t*,
    CUtensorMapInterleave, CUtensorMapSwizzle, CUtensorMapL2promotion,
    CUtensorMapFloatOOBfill);

extern "C" void kernel_launch(void* const* d_in, const int* in_sizes, int n_in,
                              void* d_out, int out_size) {
    const float* x    = (const float*)d_in[0];
    const int*   qw   = (const int*)d_in[1];
    const float* sc   = (const float*)d_in[2];
    const float* zr   = (const float*)d_in[3];
    const float* lA   = (const float*)d_in[4];
    const float* lB   = (const float*)d_in[5];
    const float* bias = (const float*)d_in[6];
    float* out = (float*)d_out;

    void* x16p = nullptr;
    void* w16p = nullptr;
    cudaGetSymbolAddress(&x16p, g_x16);
    cudaGetSymbolAddress(&w16p, g_w16);

    tmap_encode_fn enc = nullptr;
    cudaDriverEntryPointQueryResult qres;
    cudaGetDriverEntryPointByVersion("cuTensorMapEncodeTiled", (void**)&enc,
                                     12000, cudaEnableDefault, &qres);
    if (!enc) return;

    CUtensorMap tmx, tmw;
    {
        cuuint64_t dims[3]    = {D_IN, MROWS, 1};
        cuuint64_t strides[2] = {(cuuint64_t)D_IN * 2, (cuuint64_t)D_IN * MROWS * 2};
        cuuint32_t box[3]     = {BK, BM, 1};
        cuuint32_t es[3]      = {1, 1, 1};
        enc(&tmx, CU_TENSOR_MAP_DATA_TYPE_FLOAT16, 3, x16p, dims, strides, box, es,
            CU_TENSOR_MAP_INTERLEAVE_NONE, CU_TENSOR_MAP_SWIZZLE_128B,
            CU_TENSOR_MAP_L2_PROMOTION_L2_128B, CU_TENSOR_MAP_FLOAT_OOB_FILL_NONE);
    }
    {
        cuuint64_t dims[3]    = {D_IN, D_OUT, 1};
        cuuint64_t strides[2] = {(cuuint64_t)D_IN * 2, (cuuint64_t)D_IN * D_OUT * 2};
        cuuint32_t box[3]     = {BK, BN, 1};
        cuuint32_t es[3]      = {1, 1, 1};
        enc(&tmw, CU_TENSOR_MAP_DATA_TYPE_FLOAT16, 3, w16p, dims, strides, box, es,
            CU_TENSOR_MAP_INTERLEAVE_NONE, CU_TENSOR_MAP_SWIZZLE_128B,
            CU_TENSOR_MAP_L2_PROMOTION_L2_128B, CU_TENSOR_MAP_FLOAT_OOB_FILL_NONE);
    }

    // 1) cast x -> fp16 (2 float4 per thread)
    int n8 = (MROWS * D_IN) / 8;
    cast_x_kernel<<<(n8 + 255) / 256, 256>>>((const float4*)x, (uint4*)x16p, n8);

    // 2) dequant + LoRA fold -> W_eff fp16 (int4 loads)
    build_w_kernel<<<dim3(D_IN / WB_IT, D_OUT / WB_OT), 256>>>(
        (const int4*)qw, sc, zr, lA, lB, (uint2*)w16p);

    // 3) GEMM + bias
    cudaFuncSetAttribute(qlora_gemm_kernel,
                         cudaFuncAttributeMaxDynamicSharedMemorySize, SMEM_TOTAL);
    qlora_gemm_kernel<<<dim3(D_OUT / BN, MROWS / BM), 128, SMEM_TOTAL>>>(
        tmx, tmw, bias, out);
}